// round 12
// baseline (speedup 1.0000x reference)
#include <cuda_runtime.h>
#include <cuda_fp16.h>
#include <cstdint>

#define NUM_USER  200000
#define NUM_GROUP 50000
#define NROWS     (NUM_USER + NUM_GROUP)   // 250000
#define EDGES     4000000
#define DD        64
#define BB        8192

__device__ __forceinline__ int h2_as_int(__half2 h) {
    return *reinterpret_cast<int*>(&h);
}

// ---- scratch (__device__ globals; no cudaMalloc allowed) -------------------
__device__ __half g_e0[(size_t)NROWS * DD];   // fp16 concat(tables)
__device__ __half g_e1[(size_t)NROWS * DD];
__device__ __half g_e2[(size_t)NROWS * DD];
__device__ int2   g_pairs[EDGES];             // (col, val-bits) sorted by row
__device__ int    g_counts[NROWS];            // INVARIANT: zero at launch entry
__device__ int    g_row_ptr[NROWS + 1];
__device__ int    g_cursor[NROWS];

#define SCAN_ELEMS 2048
#define NBLK_SCAN  ((NROWS + SCAN_ELEMS - 1) / SCAN_ELEMS)   // 123
__device__ int   g_blockagg[NBLK_SCAN];       // aggregate+1; 0 = not ready

// ---------------------------------------------------------------------------
// 0) convert fp32 tables -> fp16 concat; ALSO: histogram rows (merged) and
//    zero the scan flags.
// ---------------------------------------------------------------------------
__global__ __launch_bounds__(256)
void convert_hist_kernel(const float4* __restrict__ ut, const float4* __restrict__ gt,
                         const int4* __restrict__ rows4)
{
    int i = blockIdx.x * blockDim.x + threadIdx.x;   // one int4 (8 halves)
    if (i < NBLK_SCAN) g_blockagg[i] = 0;

    if (i < EDGES / 4) {
        int4 r = rows4[i];
        atomicAdd(&g_counts[r.x], 1);
        atomicAdd(&g_counts[r.y], 1);
        atomicAdd(&g_counts[r.z], 1);
        atomicAdd(&g_counts[r.w], 1);
    }

    if (i >= NROWS * 8) return;
    const int USER8 = NUM_USER * 8;
    float4 lo, hi;
    if (i < USER8) { lo = ut[(size_t)i * 2]; hi = ut[(size_t)i * 2 + 1]; }
    else { size_t j = i - USER8; lo = gt[j * 2]; hi = gt[j * 2 + 1]; }
    int4 o;
    o.x = h2_as_int(__floats2half2_rn(lo.x, lo.y));
    o.y = h2_as_int(__floats2half2_rn(lo.z, lo.w));
    o.z = h2_as_int(__floats2half2_rn(hi.x, hi.y));
    o.w = h2_as_int(__floats2half2_rn(hi.z, hi.w));
    reinterpret_cast<int4*>(g_e0)[i] = o;
}

// ---------------------------------------------------------------------------
// 1) single-pass scan (decoupled lookback, 123 blocks = wave-1 resident)
// ---------------------------------------------------------------------------
__global__ __launch_bounds__(256)
void scan_fused_kernel()
{
    __shared__ int sh[256];
    __shared__ int pref[256];
    int tid = threadIdx.x;
    int bid = blockIdx.x;
    int base = bid * SCAN_ELEMS + tid * 8;

    int v[8];
    int s = 0;
    #pragma unroll
    for (int j = 0; j < 8; j++) {
        int i = base + j;
        v[j] = (i < NROWS) ? g_counts[i] : 0;
        s += v[j];
    }
    sh[tid] = s;
    __syncthreads();
    for (int off = 1; off < 256; off <<= 1) {
        int t = (tid >= off) ? sh[tid - off] : 0;
        __syncthreads();
        sh[tid] += t;
        __syncthreads();
    }
    int total = sh[255];

    if (tid == 0) atomicExch(&g_blockagg[bid], total + 1);

    int part = 0;
    if (tid < bid) {
        int a;
        do { a = atomicAdd(&g_blockagg[tid], 0); } while (a == 0);
        part = a - 1;
    }
    pref[tid] = part;
    __syncthreads();
    for (int off = 128; off > 0; off >>= 1) {
        if (tid < off) pref[tid] += pref[tid + off];
        __syncthreads();
    }
    int offset = pref[0];

    int excl = sh[tid] - s;
    int run  = offset + excl;
    #pragma unroll
    for (int j = 0; j < 8; j++) {
        int i = base + j;
        if (i < NROWS) {
            g_row_ptr[i] = run;
            g_cursor[i]  = run;
            g_counts[i]  = 0;
        }
        run += v[j];
    }
    if (bid == 0 && tid == 0) g_row_ptr[NROWS] = EDGES;
}

// ---------------------------------------------------------------------------
// 2) scatter edges into row-sorted order
// ---------------------------------------------------------------------------
__global__ __launch_bounds__(256)
void scatter_kernel(const int* __restrict__ rows, const int* __restrict__ cols,
                    const float* __restrict__ vals)
{
    int e = blockIdx.x * blockDim.x + threadIdx.x;
    if (e >= EDGES) return;
    int r   = rows[e];
    int pos = atomicAdd(&g_cursor[r], 1);
    g_pairs[pos] = make_int2(cols[e], __float_as_int(vals[e]));
}

// ---------------------------------------------------------------------------
// 3) CSR spmm, fp16 storage + HFMA2 math, unroll 4 for MLP depth.
//    8 threads per row; each owns 8 halves (one int4).
//    All 4 src gathers issued before any HFMA2 consumes them.
// ---------------------------------------------------------------------------
__device__ __forceinline__ void acc_hfma8(__half2* acc, int4 x, __half2 vv)
{
    __half2* h = reinterpret_cast<__half2*>(&x);
    #pragma unroll
    for (int i = 0; i < 4; i++)
        acc[i] = __hfma2(h[i], vv, acc[i]);
}

__global__ __launch_bounds__(256)
void spmm_csr_h_kernel(const int4* __restrict__ src, int4* __restrict__ dst)
{
    int t    = blockIdx.x * blockDim.x + threadIdx.x;
    int r    = t >> 3;
    int lane = t & 7;
    if (r >= NROWS) return;

    int p  = g_row_ptr[r];
    int pe = g_row_ptr[r + 1];

    __half2 acc[4];
    #pragma unroll
    for (int i = 0; i < 4; i++) acc[i] = __half2half2(__ushort_as_half(0));

    // head: align p to even pair index so int4 (2-edge) loads are aligned
    if ((p & 1) && p < pe) {
        int2 q = __ldg(&g_pairs[p]);
        int4 x = __ldg(&src[(size_t)q.x * 8 + lane]);
        acc_hfma8(acc, x, __float2half2_rn(__int_as_float(q.y)));
        p++;
    }

    const int4* pairs4 = reinterpret_cast<const int4*>(g_pairs);

    // main: 4 edges per iter, 4 independent src gathers in flight
    for (; p + 4 <= pe; p += 4) {
        int4 q01 = __ldg(&pairs4[p >> 1]);
        int4 q23 = __ldg(&pairs4[(p >> 1) + 1]);
        int4 x0 = __ldg(&src[(size_t)q01.x * 8 + lane]);
        int4 x1 = __ldg(&src[(size_t)q01.z * 8 + lane]);
        int4 x2 = __ldg(&src[(size_t)q23.x * 8 + lane]);
        int4 x3 = __ldg(&src[(size_t)q23.z * 8 + lane]);
        acc_hfma8(acc, x0, __float2half2_rn(__int_as_float(q01.y)));
        acc_hfma8(acc, x1, __float2half2_rn(__int_as_float(q01.w)));
        acc_hfma8(acc, x2, __float2half2_rn(__int_as_float(q23.y)));
        acc_hfma8(acc, x3, __float2half2_rn(__int_as_float(q23.w)));
    }
    // tail: 2 edges
    if (p + 2 <= pe) {
        int4 q01 = __ldg(&pairs4[p >> 1]);
        int4 x0 = __ldg(&src[(size_t)q01.x * 8 + lane]);
        int4 x1 = __ldg(&src[(size_t)q01.z * 8 + lane]);
        acc_hfma8(acc, x0, __float2half2_rn(__int_as_float(q01.y)));
        acc_hfma8(acc, x1, __float2half2_rn(__int_as_float(q01.w)));
        p += 2;
    }
    // tail: 1 edge
    if (p < pe) {
        int2 q = __ldg(&g_pairs[p]);
        int4 x = __ldg(&src[(size_t)q.x * 8 + lane]);
        acc_hfma8(acc, x, __float2half2_rn(__int_as_float(q.y)));
    }

    int4 o;
    o.x = h2_as_int(acc[0]);
    o.y = h2_as_int(acc[1]);
    o.z = h2_as_int(acc[2]);
    o.w = h2_as_int(acc[3]);
    dst[(size_t)r * 8 + lane] = o;
}

// ---------------------------------------------------------------------------
// 4) FUSED layer-3 + gather (fp32 accumulate — final output path, unchanged)
// ---------------------------------------------------------------------------
__device__ __forceinline__ void acc_fma8(float* a, int4 x, float v)
{
    __half2* h = reinterpret_cast<__half2*>(&x);
    #pragma unroll
    for (int i = 0; i < 4; i++) {
        float2 f = __half22float2(h[i]);
        a[2*i]   = fmaf(v, f.x, a[2*i]);
        a[2*i+1] = fmaf(v, f.y, a[2*i+1]);
    }
}

__global__ __launch_bounds__(256)
void l3_gather_kernel(const float4* __restrict__ ut, const float4* __restrict__ gt,
                      const int* __restrict__ ui, const int* __restrict__ pg,
                      const int* __restrict__ ng, float4* __restrict__ out)
{
    int t    = blockIdx.x * blockDim.x + threadIdx.x;
    int slot = t >> 3;              // 0 .. 3*BB-1
    int lane = t & 7;               // owns features [lane*8, lane*8+8)
    if (slot >= 3 * BB) return;

    int sec = slot / BB;            // 0=user, 1=pos, 2=neg
    int b   = slot - sec * BB;

    int r;
    const float4* tab;
    int tabrow;
    if (sec == 0)      { tabrow = ui[b]; r = tabrow;            tab = ut; }
    else if (sec == 1) { tabrow = pg[b]; r = NUM_USER + tabrow; tab = gt; }
    else               { tabrow = ng[b]; r = NUM_USER + tabrow; tab = gt; }

    int p  = __ldg(&g_row_ptr[r]);
    int pe = __ldg(&g_row_ptr[r + 1]);

    float a[8];
    #pragma unroll
    for (int i = 0; i < 8; i++) a[i] = 0.f;

    const int4* src = reinterpret_cast<const int4*>(g_e2);
    for (; p + 2 <= pe; p += 2) {
        int2 q0 = __ldg(&g_pairs[p]);
        int2 q1 = __ldg(&g_pairs[p + 1]);
        int4 x0 = __ldg(&src[(size_t)q0.x * 8 + lane]);
        int4 x1 = __ldg(&src[(size_t)q1.x * 8 + lane]);
        acc_fma8(a, x0, __int_as_float(q0.y));
        acc_fma8(a, x1, __int_as_float(q1.y));
    }
    if (p < pe) {
        int2 q0 = __ldg(&g_pairs[p]);
        int4 x0 = __ldg(&src[(size_t)q0.x * 8 + lane]);
        acc_fma8(a, x0, __int_as_float(q0.y));
    }

    float4 t0a = __ldg(&tab[(size_t)tabrow * 16 + lane * 2]);
    float4 t0b = __ldg(&tab[(size_t)tabrow * 16 + lane * 2 + 1]);

    int4 h1 = __ldg(&reinterpret_cast<const int4*>(g_e1)[(size_t)r * 8 + lane]);
    int4 h2 = __ldg(&reinterpret_cast<const int4*>(g_e2)[(size_t)r * 8 + lane]);
    float f1[8], f2[8];
    {
        __half2* hh1 = reinterpret_cast<__half2*>(&h1);
        __half2* hh2 = reinterpret_cast<__half2*>(&h2);
        #pragma unroll
        for (int i = 0; i < 4; i++) {
            float2 u1 = __half22float2(hh1[i]);
            float2 u2 = __half22float2(hh2[i]);
            f1[2*i] = u1.x; f1[2*i+1] = u1.y;
            f2[2*i] = u2.x; f2[2*i+1] = u2.y;
        }
    }

    const float s = 0.25f;
    float4 oa = make_float4((t0a.x + f1[0] + f2[0] + a[0]) * s,
                            (t0a.y + f1[1] + f2[1] + a[1]) * s,
                            (t0a.z + f1[2] + f2[2] + a[2]) * s,
                            (t0a.w + f1[3] + f2[3] + a[3]) * s);
    float4 ob = make_float4((t0b.x + f1[4] + f2[4] + a[4]) * s,
                            (t0b.y + f1[5] + f2[5] + a[5]) * s,
                            (t0b.z + f1[6] + f2[6] + a[6]) * s,
                            (t0b.w + f1[7] + f2[7] + a[7]) * s);

    size_t obase = ((size_t)sec * BB + b) * 16 + lane * 2;
    out[obase]     = oa;
    out[obase + 1] = ob;
    size_t tbase = ((size_t)(sec + 3) * BB + b) * 16 + lane * 2;
    out[tbase]     = t0a;
    out[tbase + 1] = t0b;
}

// ---------------------------------------------------------------------------
extern "C" void kernel_launch(void* const* d_in, const int* in_sizes, int n_in,
                              void* d_out, int out_size)
{
    const float* user_table  = (const float*)d_in[0];
    const float* group_table = (const float*)d_in[1];
    const float* adj_vals    = (const float*)d_in[2];
    const int*   rows        = (const int*)  d_in[3];
    const int*   cols        = (const int*)  d_in[4];
    const int*   user_inputs = (const int*)  d_in[5];
    const int*   pos_groups  = (const int*)  d_in[6];
    const int*   neg_groups  = (const int*)  d_in[7];

    __half* e0 = nullptr, * e1 = nullptr, * e2 = nullptr;
    cudaGetSymbolAddress((void**)&e0, g_e0);
    cudaGetSymbolAddress((void**)&e1, g_e1);
    cudaGetSymbolAddress((void**)&e2, g_e2);

    const int TB = 256;

    convert_hist_kernel<<<(NROWS * 8 + TB - 1) / TB, TB>>>(
        (const float4*)user_table, (const float4*)group_table,
        (const int4*)rows);
    scan_fused_kernel<<<NBLK_SCAN, TB>>>();
    scatter_kernel<<<(EDGES + TB - 1) / TB, TB>>>(rows, cols, adj_vals);

    const int grid_spmm = (NROWS * 8 + TB - 1) / TB;   // 7813

    spmm_csr_h_kernel<<<grid_spmm, TB>>>((const int4*)e0, (int4*)e1);
    spmm_csr_h_kernel<<<grid_spmm, TB>>>((const int4*)e1, (int4*)e2);

    l3_gather_kernel<<<(3 * BB * 8 + TB - 1) / TB, TB>>>(
        (const float4*)user_table, (const float4*)group_table,
        user_inputs, pos_groups, neg_groups, (float4*)d_out);
}

// round 13
// speedup vs baseline: 1.0875x; 1.0875x over previous
#include <cuda_runtime.h>
#include <cuda_fp16.h>
#include <cstdint>

#define NUM_USER  200000
#define NUM_GROUP 50000
#define NROWS     (NUM_USER + NUM_GROUP)   // 250000
#define EDGES     4000000
#define DD        64
#define BB        8192

__device__ __forceinline__ int h2_as_int(__half2 h) {
    return *reinterpret_cast<int*>(&h);
}

// ---- scratch (__device__ globals; no cudaMalloc allowed) -------------------
__device__ __half g_e0[(size_t)NROWS * DD];   // fp16 concat(tables)
__device__ __half g_e1[(size_t)NROWS * DD];
__device__ __half g_e2[(size_t)NROWS * DD];
__device__ int2   g_pairs[EDGES];             // (col, val-bits) sorted by row
__device__ int    g_counts[NROWS];            // INVARIANT: zero at launch entry
__device__ int    g_row_ptr[NROWS + 1];
__device__ int    g_cursor[NROWS];

#define SCAN_ELEMS 2048
#define NBLK_SCAN  ((NROWS + SCAN_ELEMS - 1) / SCAN_ELEMS)   // 123
__device__ int   g_blockagg[NBLK_SCAN];       // aggregate+1; 0 = not ready

// ---------------------------------------------------------------------------
// 0) convert fp32 tables -> fp16 concat; ALSO: histogram rows (merged) and
//    zero the scan flags.
// ---------------------------------------------------------------------------
__global__ __launch_bounds__(256)
void convert_hist_kernel(const float4* __restrict__ ut, const float4* __restrict__ gt,
                         const int4* __restrict__ rows4)
{
    int i = blockIdx.x * blockDim.x + threadIdx.x;   // one int4 (8 halves)
    if (i < NBLK_SCAN) g_blockagg[i] = 0;

    if (i < EDGES / 4) {
        int4 r = rows4[i];
        atomicAdd(&g_counts[r.x], 1);
        atomicAdd(&g_counts[r.y], 1);
        atomicAdd(&g_counts[r.z], 1);
        atomicAdd(&g_counts[r.w], 1);
    }

    if (i >= NROWS * 8) return;
    const int USER8 = NUM_USER * 8;
    float4 lo, hi;
    if (i < USER8) { lo = ut[(size_t)i * 2]; hi = ut[(size_t)i * 2 + 1]; }
    else { size_t j = i - USER8; lo = gt[j * 2]; hi = gt[j * 2 + 1]; }
    int4 o;
    o.x = h2_as_int(__floats2half2_rn(lo.x, lo.y));
    o.y = h2_as_int(__floats2half2_rn(lo.z, lo.w));
    o.z = h2_as_int(__floats2half2_rn(hi.x, hi.y));
    o.w = h2_as_int(__floats2half2_rn(hi.z, hi.w));
    reinterpret_cast<int4*>(g_e0)[i] = o;
}

// ---------------------------------------------------------------------------
// 1) single-pass scan (decoupled lookback, 123 blocks = wave-1 resident)
// ---------------------------------------------------------------------------
__global__ __launch_bounds__(256)
void scan_fused_kernel()
{
    __shared__ int sh[256];
    __shared__ int pref[256];
    int tid = threadIdx.x;
    int bid = blockIdx.x;
    int base = bid * SCAN_ELEMS + tid * 8;

    int v[8];
    int s = 0;
    #pragma unroll
    for (int j = 0; j < 8; j++) {
        int i = base + j;
        v[j] = (i < NROWS) ? g_counts[i] : 0;
        s += v[j];
    }
    sh[tid] = s;
    __syncthreads();
    for (int off = 1; off < 256; off <<= 1) {
        int t = (tid >= off) ? sh[tid - off] : 0;
        __syncthreads();
        sh[tid] += t;
        __syncthreads();
    }
    int total = sh[255];

    if (tid == 0) atomicExch(&g_blockagg[bid], total + 1);

    int part = 0;
    if (tid < bid) {
        int a;
        do { a = atomicAdd(&g_blockagg[tid], 0); } while (a == 0);
        part = a - 1;
    }
    pref[tid] = part;
    __syncthreads();
    for (int off = 128; off > 0; off >>= 1) {
        if (tid < off) pref[tid] += pref[tid + off];
        __syncthreads();
    }
    int offset = pref[0];

    int excl = sh[tid] - s;
    int run  = offset + excl;
    #pragma unroll
    for (int j = 0; j < 8; j++) {
        int i = base + j;
        if (i < NROWS) {
            g_row_ptr[i] = run;
            g_cursor[i]  = run;
            g_counts[i]  = 0;
        }
        run += v[j];
    }
    if (bid == 0 && tid == 0) g_row_ptr[NROWS] = EDGES;
}

// ---------------------------------------------------------------------------
// 2) scatter edges into row-sorted order (4 edges/thread, vector reads)
// ---------------------------------------------------------------------------
__global__ __launch_bounds__(256)
void scatter_kernel(const int4* __restrict__ rows4, const int4* __restrict__ cols4,
                    const float4* __restrict__ vals4)
{
    int i = blockIdx.x * blockDim.x + threadIdx.x;
    if (i >= EDGES / 4) return;
    int4   r = rows4[i];
    int4   c = cols4[i];
    float4 v = vals4[i];
    int p0 = atomicAdd(&g_cursor[r.x], 1);
    int p1 = atomicAdd(&g_cursor[r.y], 1);
    int p2 = atomicAdd(&g_cursor[r.z], 1);
    int p3 = atomicAdd(&g_cursor[r.w], 1);
    g_pairs[p0] = make_int2(c.x, __float_as_int(v.x));
    g_pairs[p1] = make_int2(c.y, __float_as_int(v.y));
    g_pairs[p2] = make_int2(c.z, __float_as_int(v.z));
    g_pairs[p3] = make_int2(c.w, __float_as_int(v.w));
}

// ---------------------------------------------------------------------------
// 3) CSR spmm — EXACT R11 known-good form (48.5us, occ 85%). DO NOT PERTURB.
//    8 threads per row; each owns 8 halves (one int4). Unroll 2. HFMA2.
// ---------------------------------------------------------------------------
__device__ __forceinline__ void acc_hfma8(__half2* acc, int4 x, __half2 vv)
{
    __half2* h = reinterpret_cast<__half2*>(&x);
    #pragma unroll
    for (int i = 0; i < 4; i++)
        acc[i] = __hfma2(h[i], vv, acc[i]);
}

__global__ __launch_bounds__(256)
void spmm_csr_h_kernel(const int4* __restrict__ src, int4* __restrict__ dst)
{
    int t    = blockIdx.x * blockDim.x + threadIdx.x;
    int r    = t >> 3;
    int lane = t & 7;
    if (r >= NROWS) return;

    int p  = g_row_ptr[r];
    int pe = g_row_ptr[r + 1];

    __half2 acc[4];
    #pragma unroll
    for (int i = 0; i < 4; i++) acc[i] = __half2half2(__ushort_as_half(0));

    for (; p + 2 <= pe; p += 2) {
        int2 q0 = __ldg(&g_pairs[p]);
        int2 q1 = __ldg(&g_pairs[p + 1]);
        int4 x0 = __ldg(&src[(size_t)q0.x * 8 + lane]);
        int4 x1 = __ldg(&src[(size_t)q1.x * 8 + lane]);
        __half2 v0 = __float2half2_rn(__int_as_float(q0.y));
        __half2 v1 = __float2half2_rn(__int_as_float(q1.y));
        acc_hfma8(acc, x0, v0);
        acc_hfma8(acc, x1, v1);
    }
    if (p < pe) {
        int2 q0 = __ldg(&g_pairs[p]);
        int4 x0 = __ldg(&src[(size_t)q0.x * 8 + lane]);
        __half2 v0 = __float2half2_rn(__int_as_float(q0.y));
        acc_hfma8(acc, x0, v0);
    }

    int4 o;
    o.x = h2_as_int(acc[0]);
    o.y = h2_as_int(acc[1]);
    o.z = h2_as_int(acc[2]);
    o.w = h2_as_int(acc[3]);
    dst[(size_t)r * 8 + lane] = o;
}

// ---------------------------------------------------------------------------
// 4) FUSED layer-3 + gather, unroll 4 (small grid: 768 blocks, latency-bound
//    — extra registers don't cost a wave here, unlike the spmm).
// ---------------------------------------------------------------------------
__device__ __forceinline__ void acc_fma8(float* a, int4 x, float v)
{
    __half2* h = reinterpret_cast<__half2*>(&x);
    #pragma unroll
    for (int i = 0; i < 4; i++) {
        float2 f = __half22float2(h[i]);
        a[2*i]   = fmaf(v, f.x, a[2*i]);
        a[2*i+1] = fmaf(v, f.y, a[2*i+1]);
    }
}

__global__ __launch_bounds__(256)
void l3_gather_kernel(const float4* __restrict__ ut, const float4* __restrict__ gt,
                      const int* __restrict__ ui, const int* __restrict__ pg,
                      const int* __restrict__ ng, float4* __restrict__ out)
{
    int t    = blockIdx.x * blockDim.x + threadIdx.x;
    int slot = t >> 3;              // 0 .. 3*BB-1
    int lane = t & 7;               // owns features [lane*8, lane*8+8)
    if (slot >= 3 * BB) return;

    int sec = slot / BB;            // 0=user, 1=pos, 2=neg
    int b   = slot - sec * BB;

    int r;
    const float4* tab;
    int tabrow;
    if (sec == 0)      { tabrow = ui[b]; r = tabrow;            tab = ut; }
    else if (sec == 1) { tabrow = pg[b]; r = NUM_USER + tabrow; tab = gt; }
    else               { tabrow = ng[b]; r = NUM_USER + tabrow; tab = gt; }

    int p  = __ldg(&g_row_ptr[r]);
    int pe = __ldg(&g_row_ptr[r + 1]);

    float a[8];
    #pragma unroll
    for (int i = 0; i < 8; i++) a[i] = 0.f;

    const int4* src = reinterpret_cast<const int4*>(g_e2);

    // unroll 4: deep MLP for this latency-bound small kernel
    for (; p + 4 <= pe; p += 4) {
        int2 q0 = __ldg(&g_pairs[p]);
        int2 q1 = __ldg(&g_pairs[p + 1]);
        int2 q2 = __ldg(&g_pairs[p + 2]);
        int2 q3 = __ldg(&g_pairs[p + 3]);
        int4 x0 = __ldg(&src[(size_t)q0.x * 8 + lane]);
        int4 x1 = __ldg(&src[(size_t)q1.x * 8 + lane]);
        int4 x2 = __ldg(&src[(size_t)q2.x * 8 + lane]);
        int4 x3 = __ldg(&src[(size_t)q3.x * 8 + lane]);
        acc_fma8(a, x0, __int_as_float(q0.y));
        acc_fma8(a, x1, __int_as_float(q1.y));
        acc_fma8(a, x2, __int_as_float(q2.y));
        acc_fma8(a, x3, __int_as_float(q3.y));
    }
    for (; p < pe; p++) {
        int2 q0 = __ldg(&g_pairs[p]);
        int4 x0 = __ldg(&src[(size_t)q0.x * 8 + lane]);
        acc_fma8(a, x0, __int_as_float(q0.y));
    }

    float4 t0a = __ldg(&tab[(size_t)tabrow * 16 + lane * 2]);
    float4 t0b = __ldg(&tab[(size_t)tabrow * 16 + lane * 2 + 1]);

    int4 h1 = __ldg(&reinterpret_cast<const int4*>(g_e1)[(size_t)r * 8 + lane]);
    int4 h2 = __ldg(&reinterpret_cast<const int4*>(g_e2)[(size_t)r * 8 + lane]);
    float f1[8], f2[8];
    {
        __half2* hh1 = reinterpret_cast<__half2*>(&h1);
        __half2* hh2 = reinterpret_cast<__half2*>(&h2);
        #pragma unroll
        for (int i = 0; i < 4; i++) {
            float2 u1 = __half22float2(hh1[i]);
            float2 u2 = __half22float2(hh2[i]);
            f1[2*i] = u1.x; f1[2*i+1] = u1.y;
            f2[2*i] = u2.x; f2[2*i+1] = u2.y;
        }
    }

    const float s = 0.25f;
    float4 oa = make_float4((t0a.x + f1[0] + f2[0] + a[0]) * s,
                            (t0a.y + f1[1] + f2[1] + a[1]) * s,
                            (t0a.z + f1[2] + f2[2] + a[2]) * s,
                            (t0a.w + f1[3] + f2[3] + a[3]) * s);
    float4 ob = make_float4((t0b.x + f1[4] + f2[4] + a[4]) * s,
                            (t0b.y + f1[5] + f2[5] + a[5]) * s,
                            (t0b.z + f1[6] + f2[6] + a[6]) * s,
                            (t0b.w + f1[7] + f2[7] + a[7]) * s);

    size_t obase = ((size_t)sec * BB + b) * 16 + lane * 2;
    out[obase]     = oa;
    out[obase + 1] = ob;
    size_t tbase = ((size_t)(sec + 3) * BB + b) * 16 + lane * 2;
    out[tbase]     = t0a;
    out[tbase + 1] = t0b;
}

// ---------------------------------------------------------------------------
extern "C" void kernel_launch(void* const* d_in, const int* in_sizes, int n_in,
                              void* d_out, int out_size)
{
    const float* user_table  = (const float*)d_in[0];
    const float* group_table = (const float*)d_in[1];
    const float* adj_vals    = (const float*)d_in[2];
    const int*   rows        = (const int*)  d_in[3];
    const int*   cols        = (const int*)  d_in[4];
    const int*   user_inputs = (const int*)  d_in[5];
    const int*   pos_groups  = (const int*)  d_in[6];
    const int*   neg_groups  = (const int*)  d_in[7];

    __half* e0 = nullptr, * e1 = nullptr, * e2 = nullptr;
    cudaGetSymbolAddress((void**)&e0, g_e0);
    cudaGetSymbolAddress((void**)&e1, g_e1);
    cudaGetSymbolAddress((void**)&e2, g_e2);

    const int TB = 256;

    convert_hist_kernel<<<(NROWS * 8 + TB - 1) / TB, TB>>>(
        (const float4*)user_table, (const float4*)group_table,
        (const int4*)rows);
    scan_fused_kernel<<<NBLK_SCAN, TB>>>();
    scatter_kernel<<<(EDGES / 4 + TB - 1) / TB, TB>>>(
        (const int4*)rows, (const int4*)cols, (const float4*)adj_vals);

    const int grid_spmm = (NROWS * 8 + TB - 1) / TB;   // 7813

    spmm_csr_h_kernel<<<grid_spmm, TB>>>((const int4*)e0, (int4*)e1);
    spmm_csr_h_kernel<<<grid_spmm, TB>>>((const int4*)e1, (int4*)e2);

    l3_gather_kernel<<<(3 * BB * 8 + TB - 1) / TB, TB>>>(
        (const float4*)user_table, (const float4*)group_table,
        user_inputs, pos_groups, neg_groups, (float4*)d_out);
}

// round 14
// speedup vs baseline: 1.1020x; 1.0133x over previous
#include <cuda_runtime.h>
#include <cuda_fp16.h>
#include <cstdint>

#define NUM_USER  200000
#define NUM_GROUP 50000
#define NROWS     (NUM_USER + NUM_GROUP)   // 250000
#define EDGES     4000000
#define DD        64
#define BB        8192

__device__ __forceinline__ int h2_as_int(__half2 h) {
    return *reinterpret_cast<int*>(&h);
}

// ---- scratch (__device__ globals; no cudaMalloc allowed) -------------------
__device__ __half g_e0[(size_t)NROWS * DD];   // fp16 concat(tables)
__device__ __half g_e1[(size_t)NROWS * DD];
__device__ __half g_e2[(size_t)NROWS * DD];
__device__ int2   g_pairs[EDGES];             // (col, val-bits) sorted by row
__device__ int    g_counts[NROWS];            // INVARIANT: zero at launch entry
__device__ int    g_row_ptr[NROWS + 1];
__device__ int    g_cursor[NROWS];

#define SCAN_ELEMS 2048
#define NBLK_SCAN  ((NROWS + SCAN_ELEMS - 1) / SCAN_ELEMS)   // 123
__device__ int   g_blockagg[NBLK_SCAN];       // aggregate+1; 0 = not ready

// ---------------------------------------------------------------------------
// 0) convert fp32 tables -> fp16 concat; ALSO: histogram rows (merged) and
//    zero the scan flags.
// ---------------------------------------------------------------------------
__global__ __launch_bounds__(256)
void convert_hist_kernel(const float4* __restrict__ ut, const float4* __restrict__ gt,
                         const int4* __restrict__ rows4)
{
    int i = blockIdx.x * blockDim.x + threadIdx.x;   // one int4 (8 halves)
    if (i < NBLK_SCAN) g_blockagg[i] = 0;

    if (i < EDGES / 4) {
        int4 r = rows4[i];
        atomicAdd(&g_counts[r.x], 1);
        atomicAdd(&g_counts[r.y], 1);
        atomicAdd(&g_counts[r.z], 1);
        atomicAdd(&g_counts[r.w], 1);
    }

    if (i >= NROWS * 8) return;
    const int USER8 = NUM_USER * 8;
    float4 lo, hi;
    if (i < USER8) { lo = ut[(size_t)i * 2]; hi = ut[(size_t)i * 2 + 1]; }
    else { size_t j = i - USER8; lo = gt[j * 2]; hi = gt[j * 2 + 1]; }
    int4 o;
    o.x = h2_as_int(__floats2half2_rn(lo.x, lo.y));
    o.y = h2_as_int(__floats2half2_rn(lo.z, lo.w));
    o.z = h2_as_int(__floats2half2_rn(hi.x, hi.y));
    o.w = h2_as_int(__floats2half2_rn(hi.z, hi.w));
    reinterpret_cast<int4*>(g_e0)[i] = o;
}

// ---------------------------------------------------------------------------
// 1) single-pass scan (decoupled lookback, 123 blocks = wave-1 resident)
// ---------------------------------------------------------------------------
__global__ __launch_bounds__(256)
void scan_fused_kernel()
{
    __shared__ int sh[256];
    __shared__ int pref[256];
    int tid = threadIdx.x;
    int bid = blockIdx.x;
    int base = bid * SCAN_ELEMS + tid * 8;

    int v[8];
    int s = 0;
    #pragma unroll
    for (int j = 0; j < 8; j++) {
        int i = base + j;
        v[j] = (i < NROWS) ? g_counts[i] : 0;
        s += v[j];
    }
    sh[tid] = s;
    __syncthreads();
    for (int off = 1; off < 256; off <<= 1) {
        int t = (tid >= off) ? sh[tid - off] : 0;
        __syncthreads();
        sh[tid] += t;
        __syncthreads();
    }
    int total = sh[255];

    if (tid == 0) atomicExch(&g_blockagg[bid], total + 1);

    int part = 0;
    if (tid < bid) {
        int a;
        do { a = atomicAdd(&g_blockagg[tid], 0); } while (a == 0);
        part = a - 1;
    }
    pref[tid] = part;
    __syncthreads();
    for (int off = 128; off > 0; off >>= 1) {
        if (tid < off) pref[tid] += pref[tid + off];
        __syncthreads();
    }
    int offset = pref[0];

    int excl = sh[tid] - s;
    int run  = offset + excl;
    #pragma unroll
    for (int j = 0; j < 8; j++) {
        int i = base + j;
        if (i < NROWS) {
            g_row_ptr[i] = run;
            g_cursor[i]  = run;
            g_counts[i]  = 0;
        }
        run += v[j];
    }
    if (bid == 0 && tid == 0) g_row_ptr[NROWS] = EDGES;
}

// ---------------------------------------------------------------------------
// 2) scatter edges into row-sorted order (scalar — R11 known-good form)
// ---------------------------------------------------------------------------
__global__ __launch_bounds__(256)
void scatter_kernel(const int* __restrict__ rows, const int* __restrict__ cols,
                    const float* __restrict__ vals)
{
    int e = blockIdx.x * blockDim.x + threadIdx.x;
    if (e >= EDGES) return;
    int r   = rows[e];
    int pos = atomicAdd(&g_cursor[r], 1);
    g_pairs[pos] = make_int2(cols[e], __float_as_int(vals[e]));
}

// ---------------------------------------------------------------------------
// 3) CSR spmm — EXACT R11 known-good form (48.5us, occ 85%). DO NOT PERTURB.
//    8 threads per row; each owns 8 halves (one int4). Unroll 2. HFMA2.
// ---------------------------------------------------------------------------
__device__ __forceinline__ void acc_hfma8(__half2* acc, int4 x, __half2 vv)
{
    __half2* h = reinterpret_cast<__half2*>(&x);
    #pragma unroll
    for (int i = 0; i < 4; i++)
        acc[i] = __hfma2(h[i], vv, acc[i]);
}

__global__ __launch_bounds__(256)
void spmm_csr_h_kernel(const int4* __restrict__ src, int4* __restrict__ dst)
{
    int t    = blockIdx.x * blockDim.x + threadIdx.x;
    int r    = t >> 3;
    int lane = t & 7;
    if (r >= NROWS) return;

    int p  = g_row_ptr[r];
    int pe = g_row_ptr[r + 1];

    __half2 acc[4];
    #pragma unroll
    for (int i = 0; i < 4; i++) acc[i] = __half2half2(__ushort_as_half(0));

    for (; p + 2 <= pe; p += 2) {
        int2 q0 = __ldg(&g_pairs[p]);
        int2 q1 = __ldg(&g_pairs[p + 1]);
        int4 x0 = __ldg(&src[(size_t)q0.x * 8 + lane]);
        int4 x1 = __ldg(&src[(size_t)q1.x * 8 + lane]);
        __half2 v0 = __float2half2_rn(__int_as_float(q0.y));
        __half2 v1 = __float2half2_rn(__int_as_float(q1.y));
        acc_hfma8(acc, x0, v0);
        acc_hfma8(acc, x1, v1);
    }
    if (p < pe) {
        int2 q0 = __ldg(&g_pairs[p]);
        int4 x0 = __ldg(&src[(size_t)q0.x * 8 + lane]);
        __half2 v0 = __float2half2_rn(__int_as_float(q0.y));
        acc_hfma8(acc, x0, v0);
    }

    int4 o;
    o.x = h2_as_int(acc[0]);
    o.y = h2_as_int(acc[1]);
    o.z = h2_as_int(acc[2]);
    o.w = h2_as_int(acc[3]);
    dst[(size_t)r * 8 + lane] = o;
}

// ---------------------------------------------------------------------------
// 4) FUSED layer-3 + gather, 16 threads per slot (WIDER parallelism, not
//    deeper per-thread work — each thread owns 4 features / uint2 gathers).
// ---------------------------------------------------------------------------
__device__ __forceinline__ void acc_fma4(float* a, uint2 x, float v)
{
    __half2 h0 = *reinterpret_cast<__half2*>(&x.x);
    __half2 h1 = *reinterpret_cast<__half2*>(&x.y);
    float2 f0 = __half22float2(h0);
    float2 f1 = __half22float2(h1);
    a[0] = fmaf(v, f0.x, a[0]);
    a[1] = fmaf(v, f0.y, a[1]);
    a[2] = fmaf(v, f1.x, a[2]);
    a[3] = fmaf(v, f1.y, a[3]);
}

__global__ __launch_bounds__(256)
void l3_gather_kernel(const float4* __restrict__ ut, const float4* __restrict__ gt,
                      const int* __restrict__ ui, const int* __restrict__ pg,
                      const int* __restrict__ ng, float4* __restrict__ out)
{
    int t    = blockIdx.x * blockDim.x + threadIdx.x;
    int slot = t >> 4;              // 0 .. 3*BB-1
    int lane = t & 15;              // owns features [lane*4, lane*4+4)
    if (slot >= 3 * BB) return;

    int sec = slot / BB;            // 0=user, 1=pos, 2=neg
    int b   = slot - sec * BB;

    int r;
    const float4* tab;
    int tabrow;
    if (sec == 0)      { tabrow = ui[b]; r = tabrow;            tab = ut; }
    else if (sec == 1) { tabrow = pg[b]; r = NUM_USER + tabrow; tab = gt; }
    else               { tabrow = ng[b]; r = NUM_USER + tabrow; tab = gt; }

    int p  = __ldg(&g_row_ptr[r]);
    int pe = __ldg(&g_row_ptr[r + 1]);

    float a[4];
    #pragma unroll
    for (int i = 0; i < 4; i++) a[i] = 0.f;

    const uint2* src = reinterpret_cast<const uint2*>(g_e2);
    for (; p + 2 <= pe; p += 2) {
        int2 q0 = __ldg(&g_pairs[p]);
        int2 q1 = __ldg(&g_pairs[p + 1]);
        uint2 x0 = __ldg(&src[(size_t)q0.x * 16 + lane]);
        uint2 x1 = __ldg(&src[(size_t)q1.x * 16 + lane]);
        acc_fma4(a, x0, __int_as_float(q0.y));
        acc_fma4(a, x1, __int_as_float(q1.y));
    }
    if (p < pe) {
        int2 q0 = __ldg(&g_pairs[p]);
        uint2 x0 = __ldg(&src[(size_t)q0.x * 16 + lane]);
        acc_fma4(a, x0, __int_as_float(q0.y));
    }

    // e0 (exact fp32 table), e1, e2 rows — this thread's 4 features
    float4 t0 = __ldg(&tab[(size_t)tabrow * 16 + lane]);

    uint2 h1 = __ldg(&reinterpret_cast<const uint2*>(g_e1)[(size_t)r * 16 + lane]);
    uint2 h2 = __ldg(&reinterpret_cast<const uint2*>(g_e2)[(size_t)r * 16 + lane]);
    float f1[4], f2[4];
    {
        __half2 a0 = *reinterpret_cast<__half2*>(&h1.x);
        __half2 a1 = *reinterpret_cast<__half2*>(&h1.y);
        __half2 b0 = *reinterpret_cast<__half2*>(&h2.x);
        __half2 b1 = *reinterpret_cast<__half2*>(&h2.y);
        float2 u0 = __half22float2(a0), u1 = __half22float2(a1);
        float2 w0 = __half22float2(b0), w1 = __half22float2(b1);
        f1[0] = u0.x; f1[1] = u0.y; f1[2] = u1.x; f1[3] = u1.y;
        f2[0] = w0.x; f2[1] = w0.y; f2[2] = w1.x; f2[3] = w1.y;
    }

    const float s = 0.25f;
    float4 o = make_float4((t0.x + f1[0] + f2[0] + a[0]) * s,
                           (t0.y + f1[1] + f2[1] + a[1]) * s,
                           (t0.z + f1[2] + f2[2] + a[2]) * s,
                           (t0.w + f1[3] + f2[3] + a[3]) * s);

    out[((size_t)sec * BB + b) * 16 + lane]       = o;
    out[((size_t)(sec + 3) * BB + b) * 16 + lane] = t0;
}

// ---------------------------------------------------------------------------
extern "C" void kernel_launch(void* const* d_in, const int* in_sizes, int n_in,
                              void* d_out, int out_size)
{
    const float* user_table  = (const float*)d_in[0];
    const float* group_table = (const float*)d_in[1];
    const float* adj_vals    = (const float*)d_in[2];
    const int*   rows        = (const int*)  d_in[3];
    const int*   cols        = (const int*)  d_in[4];
    const int*   user_inputs = (const int*)  d_in[5];
    const int*   pos_groups  = (const int*)  d_in[6];
    const int*   neg_groups  = (const int*)  d_in[7];

    __half* e0 = nullptr, * e1 = nullptr, * e2 = nullptr;
    cudaGetSymbolAddress((void**)&e0, g_e0);
    cudaGetSymbolAddress((void**)&e1, g_e1);
    cudaGetSymbolAddress((void**)&e2, g_e2);

    const int TB = 256;

    convert_hist_kernel<<<(NROWS * 8 + TB - 1) / TB, TB>>>(
        (const float4*)user_table, (const float4*)group_table,
        (const int4*)rows);
    scan_fused_kernel<<<NBLK_SCAN, TB>>>();
    scatter_kernel<<<(EDGES + TB - 1) / TB, TB>>>(rows, cols, adj_vals);

    const int grid_spmm = (NROWS * 8 + TB - 1) / TB;   // 7813

    spmm_csr_h_kernel<<<grid_spmm, TB>>>((const int4*)e0, (int4*)e1);
    spmm_csr_h_kernel<<<grid_spmm, TB>>>((const int4*)e1, (int4*)e2);

    l3_gather_kernel<<<(3 * BB * 16 + TB - 1) / TB, TB>>>(
        (const float4*)user_table, (const float4*)group_table,
        user_inputs, pos_groups, neg_groups, (float4*)d_out);
}